// round 1
// baseline (speedup 1.0000x reference)
#include <cuda_runtime.h>
#include <math.h>

#define Bb   2
#define Qn   900
#define Cn   256
#define Ncam 6
#define NP   (Bb*Ncam*Qn)   // 10800
#define BQ   (Bb*Qn)        // 1800

// ---------------- scratch (static device globals; no allocation) -------------
__device__ float  g_inv[Bb*Ncam*16];
__device__ float4 g_proj[NP];                 // x_img, y_img, invalid_flag, pad
__device__ float  g_ms[NP*Cn];                // sampled features [B,N,Q,C]
__device__ float  g_v [NP*Cn];                // after Wv        [B,N,Q,C]
__device__ float  g_q [BQ*Cn];                // query proj      [B,Q,C]
__device__ float  g_fu[BQ*Cn];                // fused           [B,Q,C]

// ---------------- K1: batched 4x4 inverse (double, partial pivot) ------------
__global__ void invert_kernel(const float* __restrict__ ext) {
    int t = threadIdx.x;
    if (t >= Bb*Ncam) return;
    const float* E = ext + t*16;
    double a[4][8];
    for (int i = 0; i < 4; i++)
        for (int j = 0; j < 4; j++) { a[i][j] = (double)E[i*4+j]; a[i][4+j] = (i==j) ? 1.0 : 0.0; }
    for (int c = 0; c < 4; c++) {
        int p = c; double mv = fabs(a[c][c]);
        for (int r = c+1; r < 4; r++) { double v = fabs(a[r][c]); if (v > mv) { mv = v; p = r; } }
        if (p != c) for (int j = 0; j < 8; j++) { double tmp = a[c][j]; a[c][j] = a[p][j]; a[p][j] = tmp; }
        double ip = 1.0 / a[c][c];
        for (int j = 0; j < 8; j++) a[c][j] *= ip;
        for (int r = 0; r < 4; r++) if (r != c) {
            double f = a[r][c];
            for (int j = 0; j < 8; j++) a[r][j] -= f * a[c][j];
        }
    }
    for (int i = 0; i < 4; i++)
        for (int j = 0; j < 4; j++) {
            float f = (float)a[i][4+j];
            if (isnan(f)) f = 0.0f;
            else if (isinf(f)) f = (f > 0.f) ? 1e6f : -1e6f;
            g_inv[t*16 + i*4 + j] = f;
        }
}

// ---------------- K2: project reference points to image plane ----------------
__global__ void project_kernel(const float* __restrict__ refpts,
                               const int*   __restrict__ mask,
                               const float* __restrict__ intr) {
    int p = blockIdx.x * blockDim.x + threadIdx.x;
    if (p >= NP) return;
    int b = p / (Ncam*Qn);
    int n = (p / Qn) % Ncam;
    int q = p % Qn;
    int bq = b*Qn + q;
    if (mask[bq] != 0) { g_proj[p] = make_float4(0.f, 0.f, 1.0f, 0.f); return; }

    float r0 = refpts[bq*3+0] * 102.4f - 51.2f;
    float r1 = refpts[bq*3+1] * 102.4f - 51.2f;
    float r2 = refpts[bq*3+2] * 102.4f - 51.2f;

    const float* iv = g_inv + (b*Ncam + n)*16;
    float p0 = iv[0]*r0 + iv[1]*r1 + iv[2]*r2  + iv[3];
    float p1 = iv[4]*r0 + iv[5]*r1 + iv[6]*r2  + iv[7];
    float p2 = iv[8]*r0 + iv[9]*r1 + iv[10]*r2 + iv[11];

    float depth = p2;
    if (isnan(depth)) depth = 10.0f;
    else if (isinf(depth)) depth = (depth > 0.f) ? 100.0f : -100.0f;
    int invalid = depth < 1.5f;
    float ds = fmaxf(depth, 1.5f);

    float cx = p0 / ds, cy = p1 / ds, cz = p2 / ds;
    const float* Km = intr + (b*Ncam + n)*9;
    float ix = Km[0]*cx + Km[1]*cy + Km[2]*cz;
    float iy = Km[3]*cx + Km[4]*cy + Km[5]*cz;
    ix = fminf(fmaxf(ix, -3000.f), 3000.f);
    iy = fminf(fmaxf(iy, -3000.f), 3000.f);
    g_proj[p] = make_float4(ix, iy, invalid ? 1.0f : 0.0f, 0.f);
}

// ---------------- K3: bilinear sampling over 4 levels -------------------------
__device__ __forceinline__ float sample_level(const float* __restrict__ f, long cambase,
                                              int H, int W, float X, float Y) {
    float fx = X * ((float)W / 800.0f);
    float fy = Y * ((float)H / 448.0f);
    float gx = fx / (float)(W-1) * 2.0f - 1.0f;
    float gy = fy / (float)(H-1) * 2.0f - 1.0f;
    gx = fminf(fmaxf(gx, -10.f), 10.f);
    gy = fminf(fmaxf(gy, -10.f), 10.f);
    float px = (gx + 1.0f) * 0.5f * (float)(W-1);
    float py = (gy + 1.0f) * 0.5f * (float)(H-1);
    float x0f = floorf(px), y0f = floorf(py);
    int x0 = (int)x0f, y0 = (int)y0f;
    float wx = px - x0f, wy = py - y0f;

    bool vx0 = (x0 >= 0)   && (x0 < W);
    bool vx1 = (x0+1 >= 0) && (x0+1 < W);
    bool vy0 = (y0 >= 0)   && (y0 < H);
    bool vy1 = (y0+1 >= 0) && (y0+1 < H);
    int xc0 = min(max(x0, 0), W-1),  xc1 = min(max(x0+1, 0), W-1);
    int yc0 = min(max(y0, 0), H-1),  yc1 = min(max(y0+1, 0), H-1);

    const float* base = f + cambase * (long)(H*W);
    float v = 0.f;
    if (vy0) {
        const float* row = base + yc0*W;
        if (vx0) v += __ldg(row + xc0) * ((1.f-wx)*(1.f-wy));
        if (vx1) v += __ldg(row + xc1) * (wx*(1.f-wy));
    }
    if (vy1) {
        const float* row = base + yc1*W;
        if (vx0) v += __ldg(row + xc0) * ((1.f-wx)*wy);
        if (vx1) v += __ldg(row + xc1) * (wx*wy);
    }
    return v;
}

__global__ void sample_kernel(const float* __restrict__ f0, const float* __restrict__ f1,
                              const float* __restrict__ f2, const float* __restrict__ f3) {
    int p = blockIdx.x;
    int c = threadIdx.x;
    float4 pr = g_proj[p];
    float acc = 0.f;
    if (pr.z == 0.0f) {
        int b = p / (Ncam*Qn);
        int n = (p / Qn) % Ncam;
        long cambase = (long)(b*Ncam + n) * Cn + c;
        acc += sample_level(f0, cambase, 112, 200, pr.x, pr.y);
        acc += sample_level(f1, cambase,  56, 100, pr.x, pr.y);
        acc += sample_level(f2, cambase,  28,  50, pr.x, pr.y);
        acc += sample_level(f3, cambase,  14,  25, pr.x, pr.y);
    }
    g_ms[(long)p*Cn + c] = acc * 0.25f;
}

// ---------------- generic SGEMM: C[M,256] = A[M,256] @ W[256,256]^T + bias ----
// BM=128, BN=64, BK=16, 256 threads, 8x4 microtile.
__global__ __launch_bounds__(256) void gemm_kernel(
    const float* __restrict__ A, const float* __restrict__ Wt,
    const float* __restrict__ bias, float* __restrict__ Cmat,
    int M, const int* __restrict__ mask) {
    __shared__ float As[16][128];
    __shared__ float Bs[16][64];
    int bm = blockIdx.y * 128;
    int bn = blockIdx.x * 64;
    int tid = threadIdx.x;
    int tx = tid & 15;   // n dim
    int ty = tid >> 4;   // m dim

    float acc[8][4];
#pragma unroll
    for (int i = 0; i < 8; i++)
#pragma unroll
        for (int j = 0; j < 4; j++) acc[i][j] = 0.f;

    for (int k0 = 0; k0 < 256; k0 += 16) {
#pragma unroll
        for (int it = 0; it < 2; it++) {
            int lin = tid + it*256;
            int row = lin >> 2;
            int kc = (lin & 3) * 4;
            int m = bm + row;
            float4 v = make_float4(0.f, 0.f, 0.f, 0.f);
            if (m < M) v = *(const float4*)(A + (long)m*256 + k0 + kc);
            As[kc+0][row] = v.x; As[kc+1][row] = v.y;
            As[kc+2][row] = v.z; As[kc+3][row] = v.w;
        }
        {
            int row = tid >> 2;
            int kc = (tid & 3) * 4;
            float4 v = *(const float4*)(Wt + (long)(bn + row)*256 + k0 + kc);
            Bs[kc+0][row] = v.x; Bs[kc+1][row] = v.y;
            Bs[kc+2][row] = v.z; Bs[kc+3][row] = v.w;
        }
        __syncthreads();
#pragma unroll
        for (int k = 0; k < 16; k++) {
            float4 a0 = *(float4*)&As[k][ty*8];
            float4 a1 = *(float4*)&As[k][ty*8 + 4];
            float4 bb = *(float4*)&Bs[k][tx*4];
            float am[8] = {a0.x,a0.y,a0.z,a0.w,a1.x,a1.y,a1.z,a1.w};
            float bnv[4] = {bb.x,bb.y,bb.z,bb.w};
#pragma unroll
            for (int i = 0; i < 8; i++)
#pragma unroll
                for (int j = 0; j < 4; j++) acc[i][j] += am[i] * bnv[j];
        }
        __syncthreads();
    }

    float4 bia = *(const float4*)(bias + bn + tx*4);
#pragma unroll
    for (int i = 0; i < 8; i++) {
        int m = bm + ty*8 + i;
        if (m < M) {
            float4 o;
            o.x = acc[i][0] + bia.x; o.y = acc[i][1] + bia.y;
            o.z = acc[i][2] + bia.z; o.w = acc[i][3] + bia.w;
            if (mask && mask[m] != 0) { o.x = 0.f; o.y = 0.f; o.z = 0.f; o.w = 0.f; }
            *(float4*)(Cmat + (long)m*256 + bn + tx*4) = o;
        }
    }
}

// ---------------- K5: max over cameras + fuse --------------------------------
__global__ void maxfuse_kernel() {
    int i = blockIdx.x * blockDim.x + threadIdx.x;
    if (i >= BQ*Cn) return;
    int bq = i / Cn, c = i % Cn;
    int b = bq / Qn, q = bq % Qn;
    float m = -3.4e38f;
#pragma unroll
    for (int n = 0; n < Ncam; n++)
        m = fmaxf(m, g_v[((long)((b*Ncam + n)*Qn) + q)*Cn + c]);
    float qv = g_q[i];
    g_fu[i] = fmaxf(qv + m, 0.f) + qv;
}

// ---------------- launch ------------------------------------------------------
extern "C" void kernel_launch(void* const* d_in, const int* in_sizes, int n_in,
                              void* d_out, int out_size) {
    const float* query  = (const float*)d_in[0];
    const float* refpts = (const float*)d_in[1];
    const int*   mask   = (const int*)  d_in[2];   // works for int32 or float32 storage
    const float* intr   = (const float*)d_in[3];
    const float* ext    = (const float*)d_in[4];
    const float* f0     = (const float*)d_in[5];
    const float* f1     = (const float*)d_in[6];
    const float* f2     = (const float*)d_in[7];
    const float* f3     = (const float*)d_in[8];
    const float* Wq     = (const float*)d_in[9];
    const float* bq     = (const float*)d_in[10];
    const float* Wv     = (const float*)d_in[11];
    const float* bv     = (const float*)d_in[12];
    const float* Wo     = (const float*)d_in[13];
    const float* bo     = (const float*)d_in[14];

    float *p_ms, *p_v, *p_q, *p_fu;
    cudaGetSymbolAddress((void**)&p_ms, g_ms);
    cudaGetSymbolAddress((void**)&p_v,  g_v);
    cudaGetSymbolAddress((void**)&p_q,  g_q);
    cudaGetSymbolAddress((void**)&p_fu, g_fu);

    invert_kernel<<<1, 32>>>(ext);
    project_kernel<<<(NP + 127)/128, 128>>>(refpts, mask, intr);
    sample_kernel<<<NP, Cn>>>(f0, f1, f2, f3);

    // q = query @ Wq^T + bq    [1800,256]
    gemm_kernel<<<dim3(4, (BQ + 127)/128), 256>>>(query, Wq, bq, p_q, BQ, nullptr);
    // v = ms @ Wv^T + bv       [10800,256]
    gemm_kernel<<<dim3(4, (NP + 127)/128), 256>>>(p_ms, Wv, bv, p_v, NP, nullptr);

    maxfuse_kernel<<<(BQ*Cn + 255)/256, 256>>>();

    // out = fused @ Wo^T + bo, masked rows -> 0
    gemm_kernel<<<dim3(4, (BQ + 127)/128), 256>>>(p_fu, Wo, bo, (float*)d_out, BQ, mask);
}

// round 2
// speedup vs baseline: 1.1938x; 1.1938x over previous
#include <cuda_runtime.h>
#include <math.h>
#include <float.h>

#define Bb   2
#define Qn   900
#define Cn   256
#define Ncam 6
#define NP   (Bb*Ncam*Qn)   // 10800
#define BQ   (Bb*Qn)        // 1800

// ---------------- scratch (static device globals; no allocation) -------------
__device__ float  g_inv[Bb*Ncam*16];
__device__ int    g_count;
__device__ int    g_map[NP];       // p -> slot or -1
__device__ float4 g_projc[NP];     // per slot: ix, iy, cam, unused
__device__ float  g_ms[NP*Cn];     // compacted sampled features
__device__ float  g_v [NP*Cn];     // compacted v rows
__device__ float  g_q [BQ*Cn];
__device__ float  g_fu[BQ*Cn];

// ---------------- K1: batched 4x4 inverse (double, partial pivot) ------------
__global__ void invert_kernel(const float* __restrict__ ext) {
    int t = threadIdx.x;
    if (t == 0) g_count = 0;
    if (t >= Bb*Ncam) return;
    const float* E = ext + t*16;
    double a[4][8];
    for (int i = 0; i < 4; i++)
        for (int j = 0; j < 4; j++) { a[i][j] = (double)E[i*4+j]; a[i][4+j] = (i==j) ? 1.0 : 0.0; }
    for (int c = 0; c < 4; c++) {
        int p = c; double mv = fabs(a[c][c]);
        for (int r = c+1; r < 4; r++) { double v = fabs(a[r][c]); if (v > mv) { mv = v; p = r; } }
        if (p != c) for (int j = 0; j < 8; j++) { double tmp = a[c][j]; a[c][j] = a[p][j]; a[p][j] = tmp; }
        double ip = 1.0 / a[c][c];
        for (int j = 0; j < 8; j++) a[c][j] *= ip;
        for (int r = 0; r < 4; r++) if (r != c) {
            double f = a[r][c];
            for (int j = 0; j < 8; j++) a[r][j] -= f * a[c][j];
        }
    }
    for (int i = 0; i < 4; i++)
        for (int j = 0; j < 4; j++) {
            float f = (float)a[i][4+j];
            if (isnan(f)) f = 0.0f;
            else if (isinf(f)) f = (f > 0.f) ? 1e6f : -1e6f;
            g_inv[t*16 + i*4 + j] = f;
        }
}

// ---------------- K2: project + candidate compaction --------------------------
__global__ void project_kernel(const float* __restrict__ refpts,
                               const int*   __restrict__ mask,
                               const float* __restrict__ intr) {
    int p = blockIdx.x * blockDim.x + threadIdx.x;
    if (p >= NP) return;
    int b = p / (Ncam*Qn);
    int n = (p / Qn) % Ncam;
    int q = p % Qn;
    int bq = b*Qn + q;
    if (mask[bq] != 0) { g_map[p] = -1; return; }

    float r0 = refpts[bq*3+0] * 102.4f - 51.2f;
    float r1 = refpts[bq*3+1] * 102.4f - 51.2f;
    float r2 = refpts[bq*3+2] * 102.4f - 51.2f;

    const float* iv = g_inv + (b*Ncam + n)*16;
    float p0 = iv[0]*r0 + iv[1]*r1 + iv[2]*r2  + iv[3];
    float p1 = iv[4]*r0 + iv[5]*r1 + iv[6]*r2  + iv[7];
    float p2 = iv[8]*r0 + iv[9]*r1 + iv[10]*r2 + iv[11];

    float depth = p2;
    if (isnan(depth)) depth = 10.0f;
    else if (isinf(depth)) depth = (depth > 0.f) ? 100.0f : -100.0f;
    bool invalid = depth < 1.5f;
    float ds = fmaxf(depth, 1.5f);

    float cx = p0 / ds, cy = p1 / ds, cz = p2 / ds;
    const float* Km = intr + (b*Ncam + n)*9;
    float ix = Km[0]*cx + Km[1]*cy + Km[2]*cz;
    float iy = Km[3]*cx + Km[4]*cy + Km[5]*cz;
    ix = fminf(fmaxf(ix, -3000.f), 3000.f);
    iy = fminf(fmaxf(iy, -3000.f), 3000.f);

    // exact union of per-level corner-valid regions == level-3 (W=25,H=14) box
    bool cand = !invalid && (ix >= -32.f) && (ix < 800.f) && (iy >= -32.f) && (iy < 448.f);
    int slot = -1;
    if (cand) {
        slot = atomicAdd(&g_count, 1);
        g_projc[slot] = make_float4(ix, iy, (float)(b*Ncam + n), 0.f);
    }
    g_map[p] = slot;
}

// ---------------- shared GEMM core: 32x64 tile, BK=32, 128 threads -----------
__device__ __forceinline__ void gemm_core(
    const float* __restrict__ A, const float* __restrict__ Wt,
    const float* __restrict__ bias, float* __restrict__ Cmat,
    int M, int bm, int bn, const int* __restrict__ omask,
    float (*As)[36], float (*Bs)[68])
{
    int tid = threadIdx.x;
    int tx = tid & 15;   // n
    int ty = tid >> 4;   // m
    float acc[4][4];
#pragma unroll
    for (int i = 0; i < 4; i++)
#pragma unroll
        for (int j = 0; j < 4; j++) acc[i][j] = 0.f;

    for (int k0 = 0; k0 < 256; k0 += 32) {
#pragma unroll
        for (int t = 0; t < 2; t++) {
            int id = tid + t*128;
            int row = id >> 3;
            int kq = (id & 7) * 4;
            int m = bm + row;
            float4 v = make_float4(0.f,0.f,0.f,0.f);
            if (m < M) v = *(const float4*)(A + (long)m*256 + k0 + kq);
            As[kq+0][row] = v.x; As[kq+1][row] = v.y;
            As[kq+2][row] = v.z; As[kq+3][row] = v.w;
        }
#pragma unroll
        for (int t = 0; t < 4; t++) {
            int id = tid + t*128;
            int row = id >> 3;
            int kq = (id & 7) * 4;
            float4 v = *(const float4*)(Wt + (long)(bn + row)*256 + k0 + kq);
            Bs[kq+0][row] = v.x; Bs[kq+1][row] = v.y;
            Bs[kq+2][row] = v.z; Bs[kq+3][row] = v.w;
        }
        __syncthreads();
#pragma unroll
        for (int k = 0; k < 32; k++) {
            float4 av = *(const float4*)&As[k][ty*4];
            float4 bb = *(const float4*)&Bs[k][tx*4];
            float am[4] = {av.x, av.y, av.z, av.w};
            float bv[4] = {bb.x, bb.y, bb.z, bb.w};
#pragma unroll
            for (int i = 0; i < 4; i++)
#pragma unroll
                for (int j = 0; j < 4; j++) acc[i][j] += am[i] * bv[j];
        }
        __syncthreads();
    }

    float4 bia = *(const float4*)(bias + bn + tx*4);
#pragma unroll
    for (int i = 0; i < 4; i++) {
        int m = bm + ty*4 + i;
        if (m < M) {
            float4 o;
            o.x = acc[i][0] + bia.x; o.y = acc[i][1] + bia.y;
            o.z = acc[i][2] + bia.z; o.w = acc[i][3] + bia.w;
            if (omask && omask[m] != 0) { o.x = 0.f; o.y = 0.f; o.z = 0.f; o.w = 0.f; }
            *(float4*)(Cmat + (long)m*256 + bn + tx*4) = o;
        }
    }
}

// ---------------- K3: fused [q-GEMM | bilinear sampling] ----------------------
#define GQ_TILES_M ((BQ + 31)/32)            // 57
#define GQ_BLOCKS  (GQ_TILES_M * 4)          // 228
#define SAMP_BLOCKS 296

__constant__ int c_H[4] = {112, 56, 28, 14};
__constant__ int c_W[4] = {200, 100, 50, 25};

__global__ __launch_bounds__(128) void fused_qsample_kernel(
    const float* __restrict__ query, const float* __restrict__ Wq,
    const float* __restrict__ bq,
    const float* __restrict__ f0, const float* __restrict__ f1,
    const float* __restrict__ f2, const float* __restrict__ f3)
{
    __shared__ float As[32][36];
    __shared__ float Bs[32][68];
    int bid = blockIdx.x;
    if (bid < GQ_BLOCKS) {
        int bm = (bid >> 2) * 32;
        int bn = (bid & 3) * 64;
        gemm_core(query, Wq, bq, g_q, BQ, bm, bn, nullptr, As, Bs);
        return;
    }
    // -------- sampling path (persistent over compacted points) --------
    int cnt = g_count;
    const float* fp[4] = {f0, f1, f2, f3};
    for (int i = bid - GQ_BLOCKS; i < cnt; i += SAMP_BLOCKS) {
        float4 pc = g_projc[i];
        float X = pc.x, Y = pc.y;
        int cam = (int)pc.z;

        int   off[4][4];
        float wei[4][4];
#pragma unroll
        for (int l = 0; l < 4; l++) {
            int H = c_H[l], W = c_W[l];
            float fx = X * ((float)W / 800.0f);
            float fy = Y * ((float)H / 448.0f);
            float gx = fminf(fmaxf(fx / (float)(W-1) * 2.0f - 1.0f, -10.f), 10.f);
            float gy = fminf(fmaxf(fy / (float)(H-1) * 2.0f - 1.0f, -10.f), 10.f);
            float px = (gx + 1.0f) * 0.5f * (float)(W-1);
            float py = (gy + 1.0f) * 0.5f * (float)(H-1);
            float x0f = floorf(px), y0f = floorf(py);
            int x0 = (int)x0f, y0 = (int)y0f;
            float wx = px - x0f, wy = py - y0f;
            bool vx0 = (x0 >= 0)   && (x0 < W);
            bool vx1 = (x0+1 >= 0) && (x0+1 < W);
            bool vy0 = (y0 >= 0)   && (y0 < H);
            bool vy1 = (y0+1 >= 0) && (y0+1 < H);
            int xc0 = min(max(x0, 0), W-1),  xc1 = min(max(x0+1, 0), W-1);
            int yc0 = min(max(y0, 0), H-1),  yc1 = min(max(y0+1, 0), H-1);
            off[l][0] = (vy0 && vx0) ? yc0*W + xc0 : -1;
            off[l][1] = (vy0 && vx1) ? yc0*W + xc1 : -1;
            off[l][2] = (vy1 && vx0) ? yc1*W + xc0 : -1;
            off[l][3] = (vy1 && vx1) ? yc1*W + xc1 : -1;
            wei[l][0] = (1.f-wx)*(1.f-wy);
            wei[l][1] = wx*(1.f-wy);
            wei[l][2] = (1.f-wx)*wy;
            wei[l][3] = wx*wy;
        }
#pragma unroll
        for (int cc = 0; cc < 2; cc++) {
            int c = threadIdx.x + cc*128;
            float acc = 0.f;
#pragma unroll
            for (int l = 0; l < 4; l++) {
                int HW = c_H[l] * c_W[l];
                const float* base = fp[l] + (long)(cam*Cn + c) * HW;
#pragma unroll
                for (int r = 0; r < 4; r++) {
                    int o = off[l][r];
                    if (o >= 0) acc += __ldg(base + o) * wei[l][r];
                }
            }
            g_ms[(long)i*Cn + c] = acc * 0.25f;
        }
    }
}

// ---------------- K4: v-GEMM over compacted rows ------------------------------
__global__ __launch_bounds__(128) void vgemm_kernel(
    const float* __restrict__ Wv, const float* __restrict__ bv)
{
    __shared__ float As[32][36];
    __shared__ float Bs[32][68];
    int M = g_count;
    int bm = blockIdx.y * 32;
    if (bm >= M) return;
    int bn = blockIdx.x * 64;
    gemm_core(g_ms, Wv, bv, g_v, M, bm, bn, nullptr, As, Bs);
}

// ---------------- K5: max over cameras + fuse --------------------------------
__global__ void maxfuse_kernel(const float* __restrict__ bv) {
    int bq = blockIdx.x;
    int c = threadIdx.x;
    int b = bq / Qn, q = bq % Qn;
    __shared__ int slots[Ncam];
    if (c < Ncam) slots[c] = g_map[(b*Ncam + c)*Qn + q];
    __syncthreads();
    float bvv = __ldg(bv + c);
    float m = -FLT_MAX;
#pragma unroll
    for (int n = 0; n < Ncam; n++) {
        int s = slots[n];
        float v = (s >= 0) ? g_v[(long)s*Cn + c] : bvv;
        m = fmaxf(m, v);
    }
    float qv = g_q[(long)bq*Cn + c];
    g_fu[(long)bq*Cn + c] = fmaxf(qv + m, 0.f) + qv;
}

// ---------------- K6: o-GEMM -------------------------------------------------
__global__ __launch_bounds__(128) void ogemm_kernel(
    const float* __restrict__ Wo, const float* __restrict__ bo,
    float* __restrict__ out, const int* __restrict__ mask)
{
    __shared__ float As[32][36];
    __shared__ float Bs[32][68];
    int bm = blockIdx.y * 32;
    int bn = blockIdx.x * 64;
    gemm_core(g_fu, Wo, bo, out, BQ, bm, bn, mask, As, Bs);
}

// ---------------- launch ------------------------------------------------------
extern "C" void kernel_launch(void* const* d_in, const int* in_sizes, int n_in,
                              void* d_out, int out_size) {
    const float* query  = (const float*)d_in[0];
    const float* refpts = (const float*)d_in[1];
    const int*   mask   = (const int*)  d_in[2];
    const float* intr   = (const float*)d_in[3];
    const float* ext    = (const float*)d_in[4];
    const float* f0     = (const float*)d_in[5];
    const float* f1     = (const float*)d_in[6];
    const float* f2     = (const float*)d_in[7];
    const float* f3     = (const float*)d_in[8];
    const float* Wq     = (const float*)d_in[9];
    const float* bq     = (const float*)d_in[10];
    const float* Wv     = (const float*)d_in[11];
    const float* bv     = (const float*)d_in[12];
    const float* Wo     = (const float*)d_in[13];
    const float* bo     = (const float*)d_in[14];

    invert_kernel<<<1, 32>>>(ext);
    project_kernel<<<(NP + 127)/128, 128>>>(refpts, mask, intr);
    fused_qsample_kernel<<<GQ_BLOCKS + SAMP_BLOCKS, 128>>>(query, Wq, bq, f0, f1, f2, f3);
    vgemm_kernel<<<dim3(4, (NP + 31)/32), 128>>>(Wv, bv);
    maxfuse_kernel<<<BQ, Cn>>>(bv);
    ogemm_kernel<<<dim3(4, (BQ + 31)/32), 128>>>(Wo, bo, (float*)d_out, mask);
}